// round 15
// baseline (speedup 1.0000x reference)
#include <cuda_runtime.h>

#define BB    8
#define ATOT  196416
#define KTOT  4576
#define BXC   4.135166556742356f   /* log(1000/16) */
#define ROWW  16
#define CH1   16
#define CHCAP 512
#define SCAP  (CH1*CHCAP)          /* 8192 */
#define NCELL 40

__constant__ int c_ln[5]    = {147456,36864,9216,2304,576};
__constant__ int c_loff[5]  = {0,147456,184320,193536,195840};
__constant__ int c_lk[5]    = {1000,1000,1000,1000,576};
__constant__ int c_lkoff[5] = {0,1000,2000,3000,4000};
/* static candidate guesses: fkey(2.0), fkey(1.5), fkey(0.5), take-all, take-all */
__constant__ unsigned c_guess[5] = {0xC0000000u, 0xBFC00000u, 0xBF000000u, 0u, 0u};

__device__ unsigned long long g_cand[NCELL][SCAP];
__device__ int                g_ccnt[NCELL][CH1];
__device__ float4 g_boxes [BB*KTOT];
__device__ float  g_scores[BB*KTOT];
__device__ int    g_valid [BB*KTOT];
__device__ int    g_keep  [BB*KTOT];
__device__ int    g_maxb  [BB];

__device__ __forceinline__ unsigned fkey(float f){
    unsigned u = __float_as_uint(f);
    return (u & 0x80000000u) ? ~u : (u | 0x80000000u);
}
__device__ __forceinline__ unsigned long long pack_ki(unsigned u, unsigned i){
    return ((unsigned long long)u << 32) | (unsigned long long)(0xFFFFFFFFu - i);
}

/* bitonic sorts, blockDim 512, n=1024; warp-confined stages use __syncwarp */
__device__ void bitonic_desc_u64(unsigned long long* a, int n){
    for (int k = 2; k <= n; k <<= 1)
        for (int j = k >> 1; j > 0; j >>= 1){
            for (int idx = threadIdx.x; idx < n; idx += blockDim.x){
                int ixj = idx ^ j;
                if (ixj > idx){
                    unsigned long long x = a[idx], y = a[ixj];
                    bool sw = ((idx & k) == 0) ? (x < y) : (x > y);
                    if (sw){ a[idx] = y; a[ixj] = x; }
                }
            }
            int jn = (j > 1) ? (j >> 1) : k;
            if (j > 16 || jn > 16) __syncthreads(); else __syncwarp();
        }
}
__device__ void bitonic_asc_u32(unsigned* a, int n){
    for (int k = 2; k <= n; k <<= 1)
        for (int j = k >> 1; j > 0; j >>= 1){
            for (int idx = threadIdx.x; idx < n; idx += blockDim.x){
                int ixj = idx ^ j;
                if (ixj > idx){
                    unsigned x = a[idx], y = a[ixj];
                    bool sw = ((idx & k) == 0) ? (x > y) : (x < y);
                    if (sw){ a[idx] = y; a[ixj] = x; }
                }
            }
            int jn = (j > 1) ? (j >> 1) : k;
            if (j > 16 || jn > 16) __syncthreads(); else __syncwarp();
        }
}

/* fast threshold find (blockDim must be 512) */
__device__ void ft_fast(const unsigned* hist, int NB, int k,
                        unsigned* wtot, int* res){
    int tid = threadIdx.x, lane = tid & 31, wid = tid >> 5;
    int BPT = NB >> 9;
    int b0 = tid * BPT;
    unsigned s = 0;
    for (int q = 0; q < BPT; ++q) s += hist[b0 + q];
    unsigned suf = s;
    #pragma unroll
    for (int d = 1; d < 32; d <<= 1){
        unsigned v = __shfl_down_sync(0xFFFFFFFFu, suf, d);
        if (lane + d < 32) suf += v;
    }
    if (lane == 0) wtot[wid] = suf;
    __syncthreads();
    if (tid < 16){
        unsigned w = wtot[tid];
        #pragma unroll
        for (int d = 1; d < 16; d <<= 1){
            unsigned v = __shfl_down_sync(0xFFFFu, w, d);
            if (tid + d < 16) w += v;
        }
        wtot[tid] = w;
    }
    __syncthreads();
    unsigned above_w = (wid + 1 < 16) ? wtot[wid + 1] : 0u;
    unsigned c = above_w + (suf - s);
    for (int q = BPT - 1; q >= 0; --q){
        unsigned h = hist[b0 + q];
        if (c < (unsigned)k && c + h >= (unsigned)k){ res[0] = b0 + q; res[1] = k - (int)c; }
        c += h;
    }
    __syncthreads();
}

/* ---------------- K1: fused candidate compaction (2x float4 per thread) ---------------- */
__global__ __launch_bounds__(256) void cand_kernel(const float* __restrict__ obj){
    __shared__ int s_cnt;
    int lev = blockIdx.x, b = blockIdx.y, ch = blockIdx.z, tid = threadIdx.x;
    int cell = b*5 + lev;
    if (lev == 0 && b == 0 && ch == 0 && tid < BB) g_maxb[tid] = 0;
    int n = c_ln[lev];
    int chunk = n / CH1;
    int s = ch * chunk;
    const float4* p4 = (const float4*)(obj + (size_t)b*ATOT + c_loff[lev] + s);
    int nv = chunk >> 2;
    unsigned G = c_guess[lev];
    int lane = tid & 31;
    if (tid == 0) s_cnt = 0;
    __syncthreads();
    for (int v0 = 0; v0 < nv; v0 += 512){      /* warp-uniform bound */
        int va = v0 + tid, vb = v0 + 256 + tid;
        unsigned long long lc[8]; int cnt = 0;
        if (va < nv){
            float4 f = p4[va];
            unsigned u0 = fkey(f.x), u1 = fkey(f.y), u2 = fkey(f.z), u3 = fkey(f.w);
            int i0 = s + 4*va;
            if (u0 >= G) lc[cnt++] = pack_ki(u0, (unsigned)i0);
            if (u1 >= G) lc[cnt++] = pack_ki(u1, (unsigned)(i0+1));
            if (u2 >= G) lc[cnt++] = pack_ki(u2, (unsigned)(i0+2));
            if (u3 >= G) lc[cnt++] = pack_ki(u3, (unsigned)(i0+3));
        }
        if (vb < nv){
            float4 f = p4[vb];
            unsigned u0 = fkey(f.x), u1 = fkey(f.y), u2 = fkey(f.z), u3 = fkey(f.w);
            int i0 = s + 4*vb;
            if (u0 >= G) lc[cnt++] = pack_ki(u0, (unsigned)i0);
            if (u1 >= G) lc[cnt++] = pack_ki(u1, (unsigned)(i0+1));
            if (u2 >= G) lc[cnt++] = pack_ki(u2, (unsigned)(i0+2));
            if (u3 >= G) lc[cnt++] = pack_ki(u3, (unsigned)(i0+3));
        }
        int incl = cnt;
        #pragma unroll
        for (int d = 1; d < 32; d <<= 1){
            int t = __shfl_up_sync(0xFFFFFFFFu, incl, d);
            if (lane >= d) incl += t;
        }
        int wtotal = __shfl_sync(0xFFFFFFFFu, incl, 31);
        int base = 0;
        if (lane == 31 && wtotal) base = atomicAdd(&s_cnt, wtotal);
        base = __shfl_sync(0xFFFFFFFFu, base, 31);
        int off = base + incl - cnt;
        for (int q = 0; q < cnt; ++q){
            int slot = off + q;
            if (slot < CHCAP) g_cand[cell][ch*CHCAP + slot] = lc[q];
        }
    }
    __syncthreads();
    if (tid == 0) g_ccnt[cell][ch] = s_cnt;
}

/* ---------------- K2: exact top-k over candidates + fused decode ---------------- */
__global__ __launch_bounds__(512) void select_kernel(const float* __restrict__ obj,
                                                     const float* __restrict__ deltas,
                                                     const float* __restrict__ anchors){
    extern __shared__ unsigned char dsm[];
    unsigned long long* scand = (unsigned long long*)dsm;       /* SCAP */
    unsigned long long* sel   = scand + SCAP;                   /* 1024 */
    unsigned* hist = (unsigned*)(sel + 1024);                   /* 2048 */
    unsigned* ties = hist + 2048;                               /* 1024 */
    __shared__ unsigned wtot[16];
    __shared__ int res2[2];
    __shared__ int co[CH1+1];
    __shared__ int s_ngt, s_neq, s_fb, s_max;

    int lev = blockIdx.x, b = blockIdx.y, tid = threadIdx.x, lane = tid & 31;
    int cell = b*5 + lev;
    int n = c_ln[lev], k = c_lk[lev];
    const float* p = obj + (size_t)b*ATOT + c_loff[lev];

    if (tid == 0){
        int acc = 0, of = 0;
        for (int ch = 0; ch < CH1; ++ch){
            co[ch] = acc;
            int cc = g_ccnt[cell][ch];
            if (cc > CHCAP){ of = 1; cc = CHCAP; }
            acc += cc;
        }
        co[CH1] = acc;
        s_fb = (of || acc < k);
        s_ngt = 0; s_neq = 0; s_max = 0;
    }
    for (int i = tid; i < 2048; i += 512) hist[i] = 0;
    __syncthreads();
    int fb = s_fb;
    int nc = co[CH1];

    /* pass 1 fused with staging (uniform base loops keep match_any convergent) */
    if (!fb){
        for (int ch = 0; ch < CH1; ++ch){
            int c0 = co[ch], cc = co[ch+1] - c0;
            for (int base = 0; base < cc; base += 512){
                int i = base + tid;
                unsigned bin = 0xFFFFFFFFu;
                if (i < cc){
                    unsigned long long cv = g_cand[cell][ch*CHCAP + i];
                    scand[c0 + i] = cv;
                    bin = (unsigned)(cv >> 32) >> 21;
                }
                unsigned mm = __match_any_sync(0xFFFFFFFFu, bin);
                if (bin != 0xFFFFFFFFu && lane == (__ffs(mm)-1)) atomicAdd(&hist[bin], __popc(mm));
            }
        }
    } else {
        for (int base = 0; base < n; base += 512){
            int i = base + tid;
            unsigned bin = 0xFFFFFFFFu;
            if (i < n) bin = fkey(p[i]) >> 21;
            unsigned mm = __match_any_sync(0xFFFFFFFFu, bin);
            if (bin != 0xFFFFFFFFu && lane == (__ffs(mm)-1)) atomicAdd(&hist[bin], __popc(mm));
        }
    }
    __syncthreads();
    ft_fast(hist, 2048, k, wtot, res2);
    unsigned t1 = (unsigned)res2[0]; int k1 = res2[1];
    for (int i = tid; i < 2048; i += 512) hist[i] = 0;
    __syncthreads();

    /* pass 2 */
    if (!fb){
        for (int base = 0; base < nc; base += 512){
            int i = base + tid;
            unsigned bin = 0xFFFFFFFFu;
            if (i < nc){
                unsigned long long cv = scand[i];
                unsigned u = (unsigned)(cv >> 32);
                unsigned b31 = u >> 21;
                if (b31 > t1){ int q = atomicAdd(&s_ngt, 1); sel[q] = cv; }
                else if (b31 == t1) bin = (u >> 10) & 0x7FFu;
            }
            unsigned mm = __match_any_sync(0xFFFFFFFFu, bin);
            if (bin != 0xFFFFFFFFu && lane == (__ffs(mm)-1)) atomicAdd(&hist[bin], __popc(mm));
        }
    } else {
        for (int base = 0; base < n; base += 512){
            int i = base + tid;
            unsigned bin = 0xFFFFFFFFu;
            if (i < n){
                unsigned u = fkey(p[i]);
                unsigned b31 = u >> 21;
                if (b31 > t1){ int q = atomicAdd(&s_ngt, 1); sel[q] = pack_ki(u, (unsigned)i); }
                else if (b31 == t1) bin = (u >> 10) & 0x7FFu;
            }
            unsigned mm = __match_any_sync(0xFFFFFFFFu, bin);
            if (bin != 0xFFFFFFFFu && lane == (__ffs(mm)-1)) atomicAdd(&hist[bin], __popc(mm));
        }
    }
    __syncthreads();
    ft_fast(hist, 2048, k1, wtot, res2);
    unsigned t2 = (unsigned)res2[0]; int k2 = res2[1];
    unsigned pre22 = (t1 << 11) | t2;
    for (int i = tid; i < 1024; i += 512) hist[i] = 0;
    __syncthreads();

    /* pass 3 */
    if (!fb){
        for (int base = 0; base < nc; base += 512){
            int i = base + tid;
            unsigned bin = 0xFFFFFFFFu;
            if (i < nc){
                unsigned u = (unsigned)(scand[i] >> 32);
                if ((u >> 10) == pre22) bin = u & 0x3FFu;
            }
            unsigned mm = __match_any_sync(0xFFFFFFFFu, bin);
            if (bin != 0xFFFFFFFFu && lane == (__ffs(mm)-1)) atomicAdd(&hist[bin], __popc(mm));
        }
    } else {
        for (int base = 0; base < n; base += 512){
            int i = base + tid;
            unsigned bin = 0xFFFFFFFFu;
            if (i < n){
                unsigned u = fkey(p[i]);
                if ((u >> 10) == pre22) bin = u & 0x3FFu;
            }
            unsigned mm = __match_any_sync(0xFFFFFFFFu, bin);
            if (bin != 0xFFFFFFFFu && lane == (__ffs(mm)-1)) atomicAdd(&hist[bin], __popc(mm));
        }
    }
    __syncthreads();
    ft_fast(hist, 1024, k2, wtot, res2);
    unsigned T = (pre22 << 10) | (unsigned)res2[0];
    int rem = res2[1];

    /* collect remaining strictly-above + ties at T */
    if (!fb){
        for (int i = tid; i < nc; i += 512){
            unsigned long long cv = scand[i];
            unsigned u = (unsigned)(cv >> 32);
            if ((u >> 21) == t1){
                if (u > T){ int q = atomicAdd(&s_ngt, 1); sel[q] = cv; }
                else if (u == T){
                    int q = atomicAdd(&s_neq, 1);
                    if (q < 1024) ties[q] = 0xFFFFFFFFu - (unsigned)(cv & 0xFFFFFFFFull);
                }
            }
        }
    } else {
        for (int i = tid; i < n; i += 512){
            unsigned u = fkey(p[i]);
            if ((u >> 21) == t1){
                if (u > T){ int q = atomicAdd(&s_ngt, 1); sel[q] = pack_ki(u, (unsigned)i); }
                else if (u == T){
                    int q = atomicAdd(&s_neq, 1);
                    if (q < 1024) ties[q] = (unsigned)i;
                }
            }
        }
    }
    __syncthreads();
    int ngt = s_ngt, neq = min(s_neq, 1024);
    if (neq > rem){
        for (int i = neq + tid; i < 1024; i += 512) ties[i] = 0xFFFFFFFFu;
        __syncthreads();
        bitonic_asc_u32(ties, 1024);
        __syncthreads();
    }
    for (int r = tid; r < rem; r += 512)
        sel[ngt + r] = ((unsigned long long)T << 32) | (unsigned long long)(0xFFFFFFFFu - ties[r]);
    for (int r = k + tid; r < 1024; r += 512) sel[r] = 0ull;
    __syncthreads();
    bitonic_desc_u64(sel, 1024);
    __syncthreads();

    /* fused decode + clip + score + validity + per-image max */
    int koff = c_lkoff[lev], off = c_loff[lev];
    float lmax = 0.f;
    for (int r = tid; r < k; r += 512){
        unsigned long long cc = sel[r];
        unsigned u = (unsigned)(cc >> 32);
        unsigned li = 0xFFFFFFFFu - (unsigned)(cc & 0xFFFFFFFFull);
        int a = off + (int)li;
        float4 an = ((const float4*)anchors)[a];
        float4 d  = ((const float4*)deltas)[(size_t)b*ATOT + a];
        float wa = an.z - an.x, ha = an.w - an.y;
        float cxa = an.x + 0.5f*wa, cya = an.y + 0.5f*ha;
        float dw = fminf(d.z, BXC), dh = fminf(d.w, BXC);
        float pcx = d.x*wa + cxa, pcy = d.y*ha + cya;
        float pw = expf(dw)*wa, ph = expf(dh)*ha;
        float x1 = pcx - 0.5f*pw, y1 = pcy - 0.5f*ph;
        float x2 = pcx + 0.5f*pw, y2 = pcy + 0.5f*ph;
        x1 = fminf(fmaxf(x1, 0.f), 1024.f);
        y1 = fminf(fmaxf(y1, 0.f), 768.f);
        x2 = fminf(fmaxf(x2, 0.f), 1024.f);
        y2 = fminf(fmaxf(y2, 0.f), 768.f);
        unsigned xb = (u & 0x80000000u) ? (u & 0x7FFFFFFFu) : ~u;
        float xo = __uint_as_float(xb);
        float sc = 1.f/(1.f + expf(-xo));
        int v = ((x2 - x1) >= 1.0f) && ((y2 - y1) >= 1.0f) && (sc >= 0.f);
        int e = b*KTOT + koff + r;
        g_boxes[e]  = make_float4(x1, y1, x2, y2);
        g_scores[e] = sc;
        g_valid[e]  = v;
        lmax = fmaxf(lmax, fmaxf(fmaxf(x1, y1), fmaxf(x2, y2)));
    }
    atomicMax(&s_max, __float_as_int(lmax));
    __syncthreads();
    if (tid == 0) atomicMax(&g_maxb[b], s_max);
}

/* ---------------- K3: fused NMS — matrix in smem + 4-wide speculative greedy ---------------- */
__global__ __launch_bounds__(512) void nms_kernel(){
    extern __shared__ unsigned char dsmn[];
    float* sx1 = (float*)dsmn;                       /* 1024 */
    float* sy1 = sx1 + 1024;
    float* sx2 = sy1 + 1024;
    float* sy2 = sx2 + 1024;
    float* sar = sy2 + 1024;
    unsigned long long* mat = (unsigned long long*)(sar + 1024);  /* 1024 x ROWW */
    __shared__ unsigned long long keepw[ROWW];
    __shared__ unsigned kb32[32];
    __shared__ unsigned char safl[1024];
    __shared__ unsigned short slist[1028];
    int lev = blockIdx.x, b = blockIdx.y, tid = threadIdx.x, lane = tid & 31;
    int m = c_lk[lev];
    int base = b*KTOT + c_lkoff[lev];
    float c = (float)lev * (__int_as_float(g_maxb[b]) + 1.0f);

    /* stage boxes (+offset) and valid ballots */
    for (int i = tid; i < 1024; i += 512){
        if (i < m){
            float4 bx = g_boxes[base + i];
            float nx1 = bx.x + c, ny1 = bx.y + c, nx2 = bx.z + c, ny2 = bx.w + c;
            sx1[i] = nx1; sy1[i] = ny1; sx2[i] = nx2; sy2[i] = ny2;
            sar[i] = (nx2 - nx1)*(ny2 - ny1);
        }
        safl[i] = 0;
        int pk = (i < m) && g_valid[base + i];
        unsigned bk = __ballot_sync(0xFFFFFFFFu, pk);
        if (lane == 0) kb32[i >> 5] = bk;
    }
    if (tid < ROWW) mat[1023*ROWW + tid] = 0ull;   /* zero pad row */
    __syncthreads();

    /* suppression matrix: thread r handles rows r and m-1-r (balanced triangular) */
    if (tid < (m >> 1)){
        #pragma unroll
        for (int half = 0; half < 2; ++half){
            int i = half ? (m - 1 - tid) : tid;
            float ax1 = sx1[i], ay1 = sy1[i], ax2 = sx2[i], ay2 = sy2[i], aa = sar[i];
            unsigned long long any = 0ull;
            #pragma unroll
            for (int w = 0; w < ROWW; ++w){
                int j0 = w << 6;
                unsigned long long bits = 0ull;
                int jend = min(j0 + 64, m);
                int jstart = max(j0, i + 1);
                for (int j = jstart; j < jend; ++j){
                    float iw = fmaxf(fminf(ax2, sx2[j]) - fmaxf(ax1, sx1[j]), 0.f);
                    float ih = fmaxf(fminf(ay2, sy2[j]) - fmaxf(ay1, sy1[j]), 0.f);
                    float inter = iw*ih;
                    if (inter > 0.7f*(aa + sar[j] - inter)) bits |= (1ull << (j - j0));
                }
                mat[i*ROWW + w] = bits; any |= bits;
            }
            safl[i] = any ? 1 : 0;
        }
    }
    __syncthreads();

    /* warp 0: suppressor list + 4-wide speculative greedy */
    if (tid < 32){
        int ns = 0;
        for (int bse = 0; bse < 1024; bse += 32){
            bool pr = safl[bse + lane] != 0;
            unsigned bl = __ballot_sync(0xFFFFFFFFu, pr);
            if (pr) slist[ns + __popc(bl & ((1u << lane) - 1))] = (unsigned short)(bse + lane);
            ns += __popc(bl);
        }
        int nsp = (ns + 3) & ~3;
        if (lane < 4) slist[ns + lane] = 1023;  /* pad (zero row, keep bit 0) */
        unsigned long long kreg = 0ull;
        if (lane < ROWW)
            kreg = ((unsigned long long)kb32[2*lane + 1] << 32) | (unsigned long long)kb32[2*lane];
        __syncwarp();
        if (ns > 0){
            int s0 = slist[0], s1 = slist[1], s2 = slist[2], s3 = slist[3];
            unsigned long long m0 = 0, m1 = 0, m2 = 0, m3 = 0;
            if (lane < ROWW){
                m0 = mat[s0*ROWW + lane]; m1 = mat[s1*ROWW + lane];
                m2 = mat[s2*ROWW + lane]; m3 = mat[s3*ROWW + lane];
            }
            for (int g = 0; g < nsp; g += 4){
                /* prefetch next group */
                int n0 = 1023, n1 = 1023, n2 = 1023, n3 = 1023;
                if (g + 4 < nsp){ n0 = slist[g+4]; n1 = slist[g+5]; n2 = slist[g+6]; n3 = slist[g+7]; }
                unsigned long long p0 = 0, p1 = 0, p2 = 0, p3 = 0;
                if (lane < ROWW){
                    p0 = mat[n0*ROWW + lane]; p1 = mat[n1*ROWW + lane];
                    p2 = mat[n2*ROWW + lane]; p3 = mat[n3*ROWW + lane];
                }
                /* keep bits (uniform source lanes; all shfls independent) */
                unsigned long long w0 = __shfl_sync(0xFFFFFFFFu, kreg, s0 >> 6);
                unsigned long long w1 = __shfl_sync(0xFFFFFFFFu, kreg, s1 >> 6);
                unsigned long long w2 = __shfl_sync(0xFFFFFFFFu, kreg, s2 >> 6);
                unsigned long long w3 = __shfl_sync(0xFFFFFFFFu, kreg, s3 >> 6);
                /* cross-suppression bits among the group (s0<s1<s2<s3) */
                unsigned long long r01 = __shfl_sync(0xFFFFFFFFu, m0, s1 >> 6);
                unsigned long long r02 = __shfl_sync(0xFFFFFFFFu, m0, s2 >> 6);
                unsigned long long r03 = __shfl_sync(0xFFFFFFFFu, m0, s3 >> 6);
                unsigned long long r12 = __shfl_sync(0xFFFFFFFFu, m1, s2 >> 6);
                unsigned long long r13 = __shfl_sync(0xFFFFFFFFu, m1, s3 >> 6);
                unsigned long long r23 = __shfl_sync(0xFFFFFFFFu, m2, s3 >> 6);
                unsigned kb0 = (unsigned)(w0 >> (s0 & 63)) & 1u;
                unsigned kb1 = (unsigned)(w1 >> (s1 & 63)) & 1u;
                unsigned kb2 = (unsigned)(w2 >> (s2 & 63)) & 1u;
                unsigned kb3 = (unsigned)(w3 >> (s3 & 63)) & 1u;
                unsigned m01 = (unsigned)(r01 >> (s1 & 63)) & 1u;
                unsigned m02 = (unsigned)(r02 >> (s2 & 63)) & 1u;
                unsigned m03 = (unsigned)(r03 >> (s3 & 63)) & 1u;
                unsigned m12 = (unsigned)(r12 >> (s2 & 63)) & 1u;
                unsigned m13 = (unsigned)(r13 >> (s3 & 63)) & 1u;
                unsigned m23 = (unsigned)(r23 >> (s3 & 63)) & 1u;
                unsigned k0 = kb0;
                unsigned k1 = kb1 & ~(k0 & m01);
                unsigned k2 = kb2 & ~(k0 & m02) & ~(k1 & m12);
                unsigned k3 = kb3 & ~(k0 & m03) & ~(k1 & m13) & ~(k2 & m23);
                unsigned long long clr = 0ull;
                if (k0 & 1u) clr |= m0;
                if (k1 & 1u) clr |= m1;
                if (k2 & 1u) clr |= m2;
                if (k3 & 1u) clr |= m3;
                kreg &= ~clr;
                s0 = n0; s1 = n1; s2 = n2; s3 = n3;
                m0 = p0; m1 = p1; m2 = p2; m3 = p3;
            }
        }
        if (lane < ROWW) keepw[lane] = kreg;
    }
    __syncthreads();
    for (int i = tid; i < m; i += 512)
        g_keep[base + i] = (int)((keepw[i >> 6] >> (i & 63)) & 1ull);
}

/* ---------------- K4: per-image post-NMS top-1000 via radix select + 1024 sort ------------- */
__global__ __launch_bounds__(512) void final_kernel(float* __restrict__ out){
    __shared__ unsigned skey[KTOT];
    __shared__ unsigned hist[2048];
    __shared__ unsigned long long sel[1024];
    __shared__ unsigned ties[1024];
    __shared__ unsigned wtot[16];
    __shared__ int res2[2];
    __shared__ int s_ngt, s_neq;

    int b = blockIdx.x, tid = threadIdx.x, lane = tid & 31;
    const int K2 = 1000;

    for (int i = tid; i < KTOT; i += 512){
        unsigned kk = 0u;
        if (g_keep[b*KTOT + i]) kk = __float_as_uint(g_scores[b*KTOT + i]) | 0x80000000u;
        skey[i] = kk;
    }
    for (int i = tid; i < 2048; i += 512) hist[i] = 0;
    if (tid == 0){ s_ngt = 0; s_neq = 0; }
    __syncthreads();
    for (int base = 0; base < KTOT; base += 512){
        int i = base + tid;
        unsigned bin = 0xFFFFFFFFu;
        if (i < KTOT) bin = skey[i] >> 21;
        unsigned mm = __match_any_sync(0xFFFFFFFFu, bin);
        if (bin != 0xFFFFFFFFu && lane == (__ffs(mm)-1)) atomicAdd(&hist[bin], __popc(mm));
    }
    __syncthreads();
    ft_fast(hist, 2048, K2, wtot, res2);
    unsigned t1 = (unsigned)res2[0]; int k1 = res2[1];
    for (int i = tid; i < 2048; i += 512) hist[i] = 0;
    __syncthreads();
    for (int base = 0; base < KTOT; base += 512){
        int i = base + tid;
        unsigned bin = 0xFFFFFFFFu;
        if (i < KTOT){
            unsigned u = skey[i];
            unsigned b31 = u >> 21;
            if (b31 > t1){ int q = atomicAdd(&s_ngt, 1); sel[q] = pack_ki(u, (unsigned)i); }
            else if (b31 == t1) bin = (u >> 10) & 0x7FFu;
        }
        unsigned mm = __match_any_sync(0xFFFFFFFFu, bin);
        if (bin != 0xFFFFFFFFu && lane == (__ffs(mm)-1)) atomicAdd(&hist[bin], __popc(mm));
    }
    __syncthreads();
    ft_fast(hist, 2048, k1, wtot, res2);
    unsigned t2 = (unsigned)res2[0]; int k2 = res2[1];
    unsigned pre22 = (t1 << 11) | t2;
    for (int i = tid; i < 1024; i += 512) hist[i] = 0;
    __syncthreads();
    for (int base = 0; base < KTOT; base += 512){
        int i = base + tid;
        unsigned bin = 0xFFFFFFFFu;
        if (i < KTOT){
            unsigned u = skey[i];
            if ((u >> 10) == pre22) bin = u & 0x3FFu;
        }
        unsigned mm = __match_any_sync(0xFFFFFFFFu, bin);
        if (bin != 0xFFFFFFFFu && lane == (__ffs(mm)-1)) atomicAdd(&hist[bin], __popc(mm));
    }
    __syncthreads();
    ft_fast(hist, 1024, k2, wtot, res2);
    unsigned T = (pre22 << 10) | (unsigned)res2[0];
    int rem = res2[1];
    for (int i = tid; i < KTOT; i += 512){
        unsigned u = skey[i];
        if ((u >> 21) == t1){
            if (u > T){ int q = atomicAdd(&s_ngt, 1); sel[q] = pack_ki(u, (unsigned)i); }
            else if (u == T){
                int q = atomicAdd(&s_neq, 1);
                if (q < 1024) ties[q] = (unsigned)i;
            }
        }
    }
    __syncthreads();
    int ngt = s_ngt, neq = min(s_neq, 1024);
    if (neq > rem){
        for (int i = neq + tid; i < 1024; i += 512) ties[i] = 0xFFFFFFFFu;
        __syncthreads();
        bitonic_asc_u32(ties, 1024);
        __syncthreads();
    }
    for (int r = tid; r < rem; r += 512)
        sel[ngt + r] = ((unsigned long long)T << 32) | (unsigned long long)(0xFFFFFFFFu - ties[r]);
    for (int r = K2 + tid; r < 1024; r += 512) sel[r] = 0ull;
    __syncthreads();
    bitonic_desc_u64(sel, 1024);
    __syncthreads();
    for (int r = tid; r < K2; r += 512){
        unsigned long long cc = sel[r];
        float* o = out + ((size_t)b*1000 + r)*5;
        if ((unsigned)(cc >> 32) & 0x80000000u){
            int pos = (int)(0xFFFFFFFFu - (unsigned)(cc & 0xFFFFFFFFull));
            float4 bx = g_boxes[b*KTOT + pos];
            o[0] = bx.x; o[1] = bx.y; o[2] = bx.z; o[3] = bx.w;
            o[4] = g_scores[b*KTOT + pos];
        } else {
            o[0] = 0.f; o[1] = 0.f; o[2] = 0.f; o[3] = 0.f; o[4] = 0.f;
        }
    }
}

extern "C" void kernel_launch(void* const* d_in, const int* in_sizes, int n_in,
                              void* d_out, int out_size){
    const float* obj     = (const float*)d_in[0];
    const float* deltas  = (const float*)d_in[1];
    const float* anchors = (const float*)d_in[2];
    float* out = (float*)d_out;

    const int DSM_SEL = SCAP*8 + 1024*8 + 2048*4 + 1024*4;       /* 86016  */
    const int DSM_NMS = 5*1024*4 + 1024*ROWW*8;                  /* 151552 */
    cudaFuncSetAttribute(select_kernel, cudaFuncAttributeMaxDynamicSharedMemorySize, DSM_SEL);
    cudaFuncSetAttribute(nms_kernel,    cudaFuncAttributeMaxDynamicSharedMemorySize, DSM_NMS);

    cand_kernel  <<<dim3(5, BB, CH1), 256>>>(obj);
    select_kernel<<<dim3(5, BB), 512, DSM_SEL>>>(obj, deltas, anchors);
    nms_kernel   <<<dim3(5, BB), 512, DSM_NMS>>>();
    final_kernel <<<BB, 512>>>(out);
}

// round 16
// speedup vs baseline: 1.7554x; 1.7554x over previous
#include <cuda_runtime.h>

#define BB    8
#define ATOT  196416
#define KTOT  4576
#define BXC   4.135166556742356f   /* log(1000/16) */
#define ROWW  16
#define CH1   16
#define CHCAP 512
#define SCAP  (CH1*CHCAP)          /* 8192 */
#define NCELL 40

__constant__ int c_ln[5]    = {147456,36864,9216,2304,576};
__constant__ int c_loff[5]  = {0,147456,184320,193536,195840};
__constant__ int c_lk[5]    = {1000,1000,1000,1000,576};
__constant__ int c_lkoff[5] = {0,1000,2000,3000,4000};
/* static candidate guesses: fkey(2.0), fkey(1.5), fkey(0.5), take-all, take-all */
__constant__ unsigned c_guess[5] = {0xC0000000u, 0xBFC00000u, 0xBF000000u, 0u, 0u};

__device__ unsigned long long g_cand[NCELL][SCAP];
__device__ int                g_ccnt[NCELL][CH1];
__device__ unsigned long long g_mat2[NCELL][1024][ROWW];
__device__ int                g_suprow2[NCELL][2][1024];
__device__ float4 g_boxes [BB*KTOT];
__device__ float  g_scores[BB*KTOT];
__device__ int    g_valid [BB*KTOT];
__device__ int    g_keep  [BB*KTOT];
__device__ int    g_maxb  [BB];

__device__ __forceinline__ unsigned fkey(float f){
    unsigned u = __float_as_uint(f);
    return (u & 0x80000000u) ? ~u : (u | 0x80000000u);
}
__device__ __forceinline__ unsigned long long pack_ki(unsigned u, unsigned i){
    return ((unsigned long long)u << 32) | (unsigned long long)(0xFFFFFFFFu - i);
}

/* bitonic sorts, blockDim 512, n=1024; warp-confined stages use __syncwarp */
__device__ void bitonic_desc_u64(unsigned long long* a, int n){
    for (int k = 2; k <= n; k <<= 1)
        for (int j = k >> 1; j > 0; j >>= 1){
            for (int idx = threadIdx.x; idx < n; idx += blockDim.x){
                int ixj = idx ^ j;
                if (ixj > idx){
                    unsigned long long x = a[idx], y = a[ixj];
                    bool sw = ((idx & k) == 0) ? (x < y) : (x > y);
                    if (sw){ a[idx] = y; a[ixj] = x; }
                }
            }
            int jn = (j > 1) ? (j >> 1) : k;
            if (j > 16 || jn > 16) __syncthreads(); else __syncwarp();
        }
}
__device__ void bitonic_asc_u32(unsigned* a, int n){
    for (int k = 2; k <= n; k <<= 1)
        for (int j = k >> 1; j > 0; j >>= 1){
            for (int idx = threadIdx.x; idx < n; idx += blockDim.x){
                int ixj = idx ^ j;
                if (ixj > idx){
                    unsigned x = a[idx], y = a[ixj];
                    bool sw = ((idx & k) == 0) ? (x > y) : (x < y);
                    if (sw){ a[idx] = y; a[ixj] = x; }
                }
            }
            int jn = (j > 1) ? (j >> 1) : k;
            if (j > 16 || jn > 16) __syncthreads(); else __syncwarp();
        }
}

/* fast threshold find (blockDim must be 512) */
__device__ void ft_fast(const unsigned* hist, int NB, int k,
                        unsigned* wtot, int* res){
    int tid = threadIdx.x, lane = tid & 31, wid = tid >> 5;
    int BPT = NB >> 9;
    int b0 = tid * BPT;
    unsigned s = 0;
    for (int q = 0; q < BPT; ++q) s += hist[b0 + q];
    unsigned suf = s;
    #pragma unroll
    for (int d = 1; d < 32; d <<= 1){
        unsigned v = __shfl_down_sync(0xFFFFFFFFu, suf, d);
        if (lane + d < 32) suf += v;
    }
    if (lane == 0) wtot[wid] = suf;
    __syncthreads();
    if (tid < 16){
        unsigned w = wtot[tid];
        #pragma unroll
        for (int d = 1; d < 16; d <<= 1){
            unsigned v = __shfl_down_sync(0xFFFFu, w, d);
            if (tid + d < 16) w += v;
        }
        wtot[tid] = w;
    }
    __syncthreads();
    unsigned above_w = (wid + 1 < 16) ? wtot[wid + 1] : 0u;
    unsigned c = above_w + (suf - s);
    for (int q = BPT - 1; q >= 0; --q){
        unsigned h = hist[b0 + q];
        if (c < (unsigned)k && c + h >= (unsigned)k){ res[0] = b0 + q; res[1] = k - (int)c; }
        c += h;
    }
    __syncthreads();
}

/* ---------------- K1: fused candidate compaction (2x float4 per thread) ---------------- */
__global__ __launch_bounds__(256) void cand_kernel(const float* __restrict__ obj){
    __shared__ int s_cnt;
    int lev = blockIdx.x, b = blockIdx.y, ch = blockIdx.z, tid = threadIdx.x;
    int cell = b*5 + lev;
    if (lev == 0 && b == 0 && ch == 0 && tid < BB) g_maxb[tid] = 0;
    int n = c_ln[lev];
    int chunk = n / CH1;
    int s = ch * chunk;
    const float4* p4 = (const float4*)(obj + (size_t)b*ATOT + c_loff[lev] + s);
    int nv = chunk >> 2;
    unsigned G = c_guess[lev];
    int lane = tid & 31;
    if (tid == 0) s_cnt = 0;
    __syncthreads();
    for (int v0 = 0; v0 < nv; v0 += 512){      /* warp-uniform bound */
        int va = v0 + tid, vb = v0 + 256 + tid;
        unsigned long long lc[8]; int cnt = 0;
        if (va < nv){
            float4 f = p4[va];
            unsigned u0 = fkey(f.x), u1 = fkey(f.y), u2 = fkey(f.z), u3 = fkey(f.w);
            int i0 = s + 4*va;
            if (u0 >= G) lc[cnt++] = pack_ki(u0, (unsigned)i0);
            if (u1 >= G) lc[cnt++] = pack_ki(u1, (unsigned)(i0+1));
            if (u2 >= G) lc[cnt++] = pack_ki(u2, (unsigned)(i0+2));
            if (u3 >= G) lc[cnt++] = pack_ki(u3, (unsigned)(i0+3));
        }
        if (vb < nv){
            float4 f = p4[vb];
            unsigned u0 = fkey(f.x), u1 = fkey(f.y), u2 = fkey(f.z), u3 = fkey(f.w);
            int i0 = s + 4*vb;
            if (u0 >= G) lc[cnt++] = pack_ki(u0, (unsigned)i0);
            if (u1 >= G) lc[cnt++] = pack_ki(u1, (unsigned)(i0+1));
            if (u2 >= G) lc[cnt++] = pack_ki(u2, (unsigned)(i0+2));
            if (u3 >= G) lc[cnt++] = pack_ki(u3, (unsigned)(i0+3));
        }
        int incl = cnt;
        #pragma unroll
        for (int d = 1; d < 32; d <<= 1){
            int t = __shfl_up_sync(0xFFFFFFFFu, incl, d);
            if (lane >= d) incl += t;
        }
        int wtotal = __shfl_sync(0xFFFFFFFFu, incl, 31);
        int base = 0;
        if (lane == 31 && wtotal) base = atomicAdd(&s_cnt, wtotal);
        base = __shfl_sync(0xFFFFFFFFu, base, 31);
        int off = base + incl - cnt;
        for (int q = 0; q < cnt; ++q){
            int slot = off + q;
            if (slot < CHCAP) g_cand[cell][ch*CHCAP + slot] = lc[q];
        }
    }
    __syncthreads();
    if (tid == 0) g_ccnt[cell][ch] = s_cnt;
}

/* ---------------- K2: exact top-k over candidates + fused decode ---------------- */
__global__ __launch_bounds__(512) void select_kernel(const float* __restrict__ obj,
                                                     const float* __restrict__ deltas,
                                                     const float* __restrict__ anchors){
    extern __shared__ unsigned char dsm[];
    unsigned long long* scand = (unsigned long long*)dsm;       /* SCAP */
    unsigned long long* sel   = scand + SCAP;                   /* 1024 */
    unsigned* hist = (unsigned*)(sel + 1024);                   /* 2048 */
    unsigned* ties = hist + 2048;                               /* 1024 */
    __shared__ unsigned wtot[16];
    __shared__ int res2[2];
    __shared__ int co[CH1+1];
    __shared__ int s_ngt, s_neq, s_fb, s_max;

    int lev = blockIdx.x, b = blockIdx.y, tid = threadIdx.x, lane = tid & 31;
    int cell = b*5 + lev;
    int n = c_ln[lev], k = c_lk[lev];
    const float* p = obj + (size_t)b*ATOT + c_loff[lev];

    if (tid == 0){
        int acc = 0, of = 0;
        for (int ch = 0; ch < CH1; ++ch){
            co[ch] = acc;
            int cc = g_ccnt[cell][ch];
            if (cc > CHCAP){ of = 1; cc = CHCAP; }
            acc += cc;
        }
        co[CH1] = acc;
        s_fb = (of || acc < k);
        s_ngt = 0; s_neq = 0; s_max = 0;
    }
    __syncthreads();
    int fb = s_fb;
    int nc = co[CH1];

    for (int i = tid; i < 2048; i += 512) hist[i] = 0;
    if (!fb){
        for (int ch = 0; ch < CH1; ++ch){
            int c0 = co[ch], cc = co[ch+1] - c0;
            for (int i = tid; i < cc; i += 512) scand[c0 + i] = g_cand[cell][ch*CHCAP + i];
        }
    }
    __syncthreads();

    /* pass 1: top 11 bits */
    if (!fb){
        for (int base = 0; base < nc; base += 512){
            int i = base + tid;
            unsigned bin = 0xFFFFFFFFu;
            if (i < nc) bin = (unsigned)(scand[i] >> 32) >> 21;
            unsigned mm = __match_any_sync(0xFFFFFFFFu, bin);
            if (bin != 0xFFFFFFFFu && lane == (__ffs(mm)-1)) atomicAdd(&hist[bin], __popc(mm));
        }
    } else {
        for (int base = 0; base < n; base += 512){
            int i = base + tid;
            unsigned bin = 0xFFFFFFFFu;
            if (i < n) bin = fkey(p[i]) >> 21;
            unsigned mm = __match_any_sync(0xFFFFFFFFu, bin);
            if (bin != 0xFFFFFFFFu && lane == (__ffs(mm)-1)) atomicAdd(&hist[bin], __popc(mm));
        }
    }
    __syncthreads();
    ft_fast(hist, 2048, k, wtot, res2);
    unsigned t1 = (unsigned)res2[0]; int k1 = res2[1];
    for (int i = tid; i < 2048; i += 512) hist[i] = 0;
    __syncthreads();

    /* pass 2 */
    if (!fb){
        for (int base = 0; base < nc; base += 512){
            int i = base + tid;
            unsigned bin = 0xFFFFFFFFu;
            if (i < nc){
                unsigned long long cv = scand[i];
                unsigned u = (unsigned)(cv >> 32);
                unsigned b31 = u >> 21;
                if (b31 > t1){ int q = atomicAdd(&s_ngt, 1); sel[q] = cv; }
                else if (b31 == t1) bin = (u >> 10) & 0x7FFu;
            }
            unsigned mm = __match_any_sync(0xFFFFFFFFu, bin);
            if (bin != 0xFFFFFFFFu && lane == (__ffs(mm)-1)) atomicAdd(&hist[bin], __popc(mm));
        }
    } else {
        for (int base = 0; base < n; base += 512){
            int i = base + tid;
            unsigned bin = 0xFFFFFFFFu;
            if (i < n){
                unsigned u = fkey(p[i]);
                unsigned b31 = u >> 21;
                if (b31 > t1){ int q = atomicAdd(&s_ngt, 1); sel[q] = pack_ki(u, (unsigned)i); }
                else if (b31 == t1) bin = (u >> 10) & 0x7FFu;
            }
            unsigned mm = __match_any_sync(0xFFFFFFFFu, bin);
            if (bin != 0xFFFFFFFFu && lane == (__ffs(mm)-1)) atomicAdd(&hist[bin], __popc(mm));
        }
    }
    __syncthreads();
    ft_fast(hist, 2048, k1, wtot, res2);
    unsigned t2 = (unsigned)res2[0]; int k2 = res2[1];
    unsigned pre22 = (t1 << 11) | t2;
    for (int i = tid; i < 1024; i += 512) hist[i] = 0;
    __syncthreads();

    /* pass 3 */
    if (!fb){
        for (int base = 0; base < nc; base += 512){
            int i = base + tid;
            unsigned bin = 0xFFFFFFFFu;
            if (i < nc){
                unsigned u = (unsigned)(scand[i] >> 32);
                if ((u >> 10) == pre22) bin = u & 0x3FFu;
            }
            unsigned mm = __match_any_sync(0xFFFFFFFFu, bin);
            if (bin != 0xFFFFFFFFu && lane == (__ffs(mm)-1)) atomicAdd(&hist[bin], __popc(mm));
        }
    } else {
        for (int base = 0; base < n; base += 512){
            int i = base + tid;
            unsigned bin = 0xFFFFFFFFu;
            if (i < n){
                unsigned u = fkey(p[i]);
                if ((u >> 10) == pre22) bin = u & 0x3FFu;
            }
            unsigned mm = __match_any_sync(0xFFFFFFFFu, bin);
            if (bin != 0xFFFFFFFFu && lane == (__ffs(mm)-1)) atomicAdd(&hist[bin], __popc(mm));
        }
    }
    __syncthreads();
    ft_fast(hist, 1024, k2, wtot, res2);
    unsigned T = (pre22 << 10) | (unsigned)res2[0];
    int rem = res2[1];

    /* collect remaining strictly-above + ties at T */
    if (!fb){
        for (int i = tid; i < nc; i += 512){
            unsigned long long cv = scand[i];
            unsigned u = (unsigned)(cv >> 32);
            if ((u >> 21) == t1){
                if (u > T){ int q = atomicAdd(&s_ngt, 1); sel[q] = cv; }
                else if (u == T){
                    int q = atomicAdd(&s_neq, 1);
                    if (q < 1024) ties[q] = 0xFFFFFFFFu - (unsigned)(cv & 0xFFFFFFFFull);
                }
            }
        }
    } else {
        for (int i = tid; i < n; i += 512){
            unsigned u = fkey(p[i]);
            if ((u >> 21) == t1){
                if (u > T){ int q = atomicAdd(&s_ngt, 1); sel[q] = pack_ki(u, (unsigned)i); }
                else if (u == T){
                    int q = atomicAdd(&s_neq, 1);
                    if (q < 1024) ties[q] = (unsigned)i;
                }
            }
        }
    }
    __syncthreads();
    int ngt = s_ngt, neq = min(s_neq, 1024);
    if (neq > rem){
        for (int i = neq + tid; i < 1024; i += 512) ties[i] = 0xFFFFFFFFu;
        __syncthreads();
        bitonic_asc_u32(ties, 1024);
        __syncthreads();
    }
    for (int r = tid; r < rem; r += 512)
        sel[ngt + r] = ((unsigned long long)T << 32) | (unsigned long long)(0xFFFFFFFFu - ties[r]);
    for (int r = k + tid; r < 1024; r += 512) sel[r] = 0ull;
    __syncthreads();
    bitonic_desc_u64(sel, 1024);
    __syncthreads();

    /* fused decode + clip + score + validity + per-image max */
    int koff = c_lkoff[lev], off = c_loff[lev];
    float lmax = 0.f;
    for (int r = tid; r < k; r += 512){
        unsigned long long cc = sel[r];
        unsigned u = (unsigned)(cc >> 32);
        unsigned li = 0xFFFFFFFFu - (unsigned)(cc & 0xFFFFFFFFull);
        int a = off + (int)li;
        float4 an = ((const float4*)anchors)[a];
        float4 d  = ((const float4*)deltas)[(size_t)b*ATOT + a];
        float wa = an.z - an.x, ha = an.w - an.y;
        float cxa = an.x + 0.5f*wa, cya = an.y + 0.5f*ha;
        float dw = fminf(d.z, BXC), dh = fminf(d.w, BXC);
        float pcx = d.x*wa + cxa, pcy = d.y*ha + cya;
        float pw = expf(dw)*wa, ph = expf(dh)*ha;
        float x1 = pcx - 0.5f*pw, y1 = pcy - 0.5f*ph;
        float x2 = pcx + 0.5f*pw, y2 = pcy + 0.5f*ph;
        x1 = fminf(fmaxf(x1, 0.f), 1024.f);
        y1 = fminf(fmaxf(y1, 0.f), 768.f);
        x2 = fminf(fmaxf(x2, 0.f), 1024.f);
        y2 = fminf(fmaxf(y2, 0.f), 768.f);
        unsigned xb = (u & 0x80000000u) ? (u & 0x7FFFFFFFu) : ~u;
        float xo = __uint_as_float(xb);
        float sc = 1.f/(1.f + expf(-xo));
        int v = ((x2 - x1) >= 1.0f) && ((y2 - y1) >= 1.0f) && (sc >= 0.f);
        int e = b*KTOT + koff + r;
        g_boxes[e]  = make_float4(x1, y1, x2, y2);
        g_scores[e] = sc;
        g_valid[e]  = v;
        lmax = fmaxf(lmax, fmaxf(fmaxf(x1, y1), fmaxf(x2, y2)));
    }
    atomicMax(&s_max, __float_as_int(lmax));
    __syncthreads();
    if (tid == 0) atomicMax(&g_maxb[b], s_max);
}

/* ---------------- K3a: NMS suppression matrix (triangular, row+word-split) ---------------- */
__global__ __launch_bounds__(128) void nmsA_kernel(){
    __shared__ float sx1[1024], sy1[1024], sx2[1024], sy2[1024], sar[1024];
    int lev = blockIdx.x, b = blockIdx.y, z = blockIdx.z, tid = threadIdx.x;
    int cell = b*5 + lev;
    int m = c_lk[lev];
    int base = b*KTOT + c_lkoff[lev];
    int zr = z >> 1, half = z & 1;
    float c = (float)lev * (__int_as_float(g_maxb[b]) + 1.0f);
    for (int i = tid; i < m; i += 128){
        float4 bx = g_boxes[base + i];
        float nx1 = bx.x + c, ny1 = bx.y + c, nx2 = bx.z + c, ny2 = bx.w + c;
        sx1[i] = nx1; sy1[i] = ny1; sx2[i] = nx2; sy2[i] = ny2;
        sar[i] = (nx2 - nx1)*(ny2 - ny1);
    }
    __syncthreads();
    int w0 = half * 8;
    for (int i = zr + 8*tid; i < m; i += 1024){
        float ax1 = sx1[i], ay1 = sy1[i], ax2 = sx2[i], ay2 = sy2[i], aa = sar[i];
        unsigned long long wr[8];
        unsigned long long any = 0ull;
        #pragma unroll
        for (int ww = 0; ww < 8; ++ww){
            int w = w0 + ww;
            int j0 = w << 6;
            unsigned long long bits = 0ull;
            int jend = min(j0 + 64, m);
            int jstart = max(j0, i + 1);
            for (int j = jstart; j < jend; ++j){
                float iw = fmaxf(fminf(ax2, sx2[j]) - fmaxf(ax1, sx1[j]), 0.f);
                float ih = fmaxf(fminf(ay2, sy2[j]) - fmaxf(ay1, sy1[j]), 0.f);
                float inter = iw*ih;
                if (inter > 0.7f*(aa + sar[j] - inter)) bits |= (1ull << (j - j0));
            }
            wr[ww] = bits; any |= bits;
        }
        g_suprow2[cell][half][i] = any ? 1 : 0;   /* unconditional: deterministic, no init */
        if (any){
            #pragma unroll
            for (int ww = 0; ww < 8; ++ww) g_mat2[cell][i][w0 + ww] = wr[ww];
        }
    }
}

/* ---------------- K3b: serial greedy, register keep + 4-wide speculative groups ----------- */
__global__ __launch_bounds__(512) void nmsB_kernel(){
    extern __shared__ unsigned long long mat[];   /* 1024 x ROWW */
    __shared__ unsigned long long keepw[ROWW];
    __shared__ unsigned kb32[32];
    __shared__ unsigned char sf0[1024], sf1[1024];
    __shared__ unsigned short slist[1028];
    int lev = blockIdx.x, b = blockIdx.y, tid = threadIdx.x, lane = tid & 31;
    int cell = b*5 + lev;
    int m = c_lk[lev];
    int base = b*KTOT + c_lkoff[lev];
    for (int i = tid; i < 1024; i += 512){
        int f0 = (i < m) ? g_suprow2[cell][0][i] : 0;
        int f1 = (i < m) ? g_suprow2[cell][1][i] : 0;
        sf0[i] = (unsigned char)f0; sf1[i] = (unsigned char)f1;
        int pk = (i < m) && g_valid[base + i];
        unsigned bk = __ballot_sync(0xFFFFFFFFu, pk);
        if (lane == 0) kb32[i >> 5] = bk;
    }
    __syncthreads();
    /* load valid halves of suppressor rows; zero the other half; zero pad row 1023 */
    for (int t = tid; t < 1024*ROWW; t += 512){
        int i = t >> 4, w = t & (ROWW - 1);
        int f0 = sf0[i], f1 = sf1[i];
        if (f0 | f1) mat[t] = ((w < 8) ? f0 : f1) ? g_mat2[cell][i][w] : 0ull;
        if (i == 1023 && !(f0 | f1)) mat[t] = 0ull;
    }
    __syncthreads();
    if (tid < 32){
        /* ordered suppressor list via ballots */
        int ns = 0;
        for (int bse = 0; bse < 1024; bse += 32){
            int i = bse + lane;
            bool pr = (sf0[i] | sf1[i]) != 0;
            unsigned bl = __ballot_sync(0xFFFFFFFFu, pr);
            if (pr) slist[ns + __popc(bl & ((1u << lane) - 1))] = (unsigned short)i;
            ns += __popc(bl);
        }
        int nsp = (ns + 3) & ~3;
        if (lane < 4) slist[ns + lane] = 1023;   /* pad: zero mat row, keep bit 0 */
        unsigned long long kreg = 0ull;
        if (lane < ROWW)
            kreg = ((unsigned long long)kb32[2*lane + 1] << 32) | (unsigned long long)kb32[2*lane];
        __syncwarp();
        if (ns > 0){
            int s0 = slist[0], s1 = slist[1], s2 = slist[2], s3 = slist[3];
            unsigned long long m0 = 0, m1 = 0, m2 = 0, m3 = 0;
            if (lane < ROWW){
                m0 = mat[s0*ROWW + lane]; m1 = mat[s1*ROWW + lane];
                m2 = mat[s2*ROWW + lane]; m3 = mat[s3*ROWW + lane];
            }
            for (int g = 0; g < nsp; g += 4){
                int n0 = 1023, n1 = 1023, n2 = 1023, n3 = 1023;
                if (g + 4 < nsp){ n0 = slist[g+4]; n1 = slist[g+5]; n2 = slist[g+6]; n3 = slist[g+7]; }
                unsigned long long p0 = 0, p1 = 0, p2 = 0, p3 = 0;
                if (lane < ROWW){
                    p0 = mat[n0*ROWW + lane]; p1 = mat[n1*ROWW + lane];
                    p2 = mat[n2*ROWW + lane]; p3 = mat[n3*ROWW + lane];
                }
                unsigned long long w0 = __shfl_sync(0xFFFFFFFFu, kreg, s0 >> 6);
                unsigned long long w1 = __shfl_sync(0xFFFFFFFFu, kreg, s1 >> 6);
                unsigned long long w2 = __shfl_sync(0xFFFFFFFFu, kreg, s2 >> 6);
                unsigned long long w3 = __shfl_sync(0xFFFFFFFFu, kreg, s3 >> 6);
                unsigned long long r01 = __shfl_sync(0xFFFFFFFFu, m0, s1 >> 6);
                unsigned long long r02 = __shfl_sync(0xFFFFFFFFu, m0, s2 >> 6);
                unsigned long long r03 = __shfl_sync(0xFFFFFFFFu, m0, s3 >> 6);
                unsigned long long r12 = __shfl_sync(0xFFFFFFFFu, m1, s2 >> 6);
                unsigned long long r13 = __shfl_sync(0xFFFFFFFFu, m1, s3 >> 6);
                unsigned long long r23 = __shfl_sync(0xFFFFFFFFu, m2, s3 >> 6);
                unsigned kb0 = (unsigned)(w0 >> (s0 & 63)) & 1u;
                unsigned kb1 = (unsigned)(w1 >> (s1 & 63)) & 1u;
                unsigned kb2 = (unsigned)(w2 >> (s2 & 63)) & 1u;
                unsigned kb3 = (unsigned)(w3 >> (s3 & 63)) & 1u;
                unsigned m01 = (unsigned)(r01 >> (s1 & 63)) & 1u;
                unsigned m02 = (unsigned)(r02 >> (s2 & 63)) & 1u;
                unsigned m03 = (unsigned)(r03 >> (s3 & 63)) & 1u;
                unsigned m12 = (unsigned)(r12 >> (s2 & 63)) & 1u;
                unsigned m13 = (unsigned)(r13 >> (s3 & 63)) & 1u;
                unsigned m23 = (unsigned)(r23 >> (s3 & 63)) & 1u;
                unsigned k0 = kb0;
                unsigned k1 = kb1 & ~(k0 & m01);
                unsigned k2 = kb2 & ~(k0 & m02) & ~(k1 & m12);
                unsigned k3 = kb3 & ~(k0 & m03) & ~(k1 & m13) & ~(k2 & m23);
                unsigned long long clr = 0ull;
                if (k0 & 1u) clr |= m0;
                if (k1 & 1u) clr |= m1;
                if (k2 & 1u) clr |= m2;
                if (k3 & 1u) clr |= m3;
                kreg &= ~clr;
                s0 = n0; s1 = n1; s2 = n2; s3 = n3;
                m0 = p0; m1 = p1; m2 = p2; m3 = p3;
            }
        }
        if (lane < ROWW) keepw[lane] = kreg;
    }
    __syncthreads();
    for (int i = tid; i < m; i += 512)
        g_keep[base + i] = (int)((keepw[i >> 6] >> (i & 63)) & 1ull);
}

/* ---------------- K4: per-image post-NMS top-1000 via radix select + 1024 sort ------------- */
__global__ __launch_bounds__(512) void final_kernel(float* __restrict__ out){
    __shared__ unsigned skey[KTOT];
    __shared__ unsigned hist[2048];
    __shared__ unsigned long long sel[1024];
    __shared__ unsigned ties[1024];
    __shared__ unsigned wtot[16];
    __shared__ int res2[2];
    __shared__ int s_ngt, s_neq;

    int b = blockIdx.x, tid = threadIdx.x, lane = tid & 31;
    const int K2 = 1000;

    for (int i = tid; i < KTOT; i += 512){
        unsigned kk = 0u;
        if (g_keep[b*KTOT + i]) kk = __float_as_uint(g_scores[b*KTOT + i]) | 0x80000000u;
        skey[i] = kk;
    }
    for (int i = tid; i < 2048; i += 512) hist[i] = 0;
    if (tid == 0){ s_ngt = 0; s_neq = 0; }
    __syncthreads();
    for (int base = 0; base < KTOT; base += 512){
        int i = base + tid;
        unsigned bin = 0xFFFFFFFFu;
        if (i < KTOT) bin = skey[i] >> 21;
        unsigned mm = __match_any_sync(0xFFFFFFFFu, bin);
        if (bin != 0xFFFFFFFFu && lane == (__ffs(mm)-1)) atomicAdd(&hist[bin], __popc(mm));
    }
    __syncthreads();
    ft_fast(hist, 2048, K2, wtot, res2);
    unsigned t1 = (unsigned)res2[0]; int k1 = res2[1];
    for (int i = tid; i < 2048; i += 512) hist[i] = 0;
    __syncthreads();
    for (int base = 0; base < KTOT; base += 512){
        int i = base + tid;
        unsigned bin = 0xFFFFFFFFu;
        if (i < KTOT){
            unsigned u = skey[i];
            unsigned b31 = u >> 21;
            if (b31 > t1){ int q = atomicAdd(&s_ngt, 1); sel[q] = pack_ki(u, (unsigned)i); }
            else if (b31 == t1) bin = (u >> 10) & 0x7FFu;
        }
        unsigned mm = __match_any_sync(0xFFFFFFFFu, bin);
        if (bin != 0xFFFFFFFFu && lane == (__ffs(mm)-1)) atomicAdd(&hist[bin], __popc(mm));
    }
    __syncthreads();
    ft_fast(hist, 2048, k1, wtot, res2);
    unsigned t2 = (unsigned)res2[0]; int k2 = res2[1];
    unsigned pre22 = (t1 << 11) | t2;
    for (int i = tid; i < 1024; i += 512) hist[i] = 0;
    __syncthreads();
    for (int base = 0; base < KTOT; base += 512){
        int i = base + tid;
        unsigned bin = 0xFFFFFFFFu;
        if (i < KTOT){
            unsigned u = skey[i];
            if ((u >> 10) == pre22) bin = u & 0x3FFu;
        }
        unsigned mm = __match_any_sync(0xFFFFFFFFu, bin);
        if (bin != 0xFFFFFFFFu && lane == (__ffs(mm)-1)) atomicAdd(&hist[bin], __popc(mm));
    }
    __syncthreads();
    ft_fast(hist, 1024, k2, wtot, res2);
    unsigned T = (pre22 << 10) | (unsigned)res2[0];
    int rem = res2[1];
    for (int i = tid; i < KTOT; i += 512){
        unsigned u = skey[i];
        if ((u >> 21) == t1){
            if (u > T){ int q = atomicAdd(&s_ngt, 1); sel[q] = pack_ki(u, (unsigned)i); }
            else if (u == T){
                int q = atomicAdd(&s_neq, 1);
                if (q < 1024) ties[q] = (unsigned)i;
            }
        }
    }
    __syncthreads();
    int ngt = s_ngt, neq = min(s_neq, 1024);
    if (neq > rem){
        for (int i = neq + tid; i < 1024; i += 512) ties[i] = 0xFFFFFFFFu;
        __syncthreads();
        bitonic_asc_u32(ties, 1024);
        __syncthreads();
    }
    for (int r = tid; r < rem; r += 512)
        sel[ngt + r] = ((unsigned long long)T << 32) | (unsigned long long)(0xFFFFFFFFu - ties[r]);
    for (int r = K2 + tid; r < 1024; r += 512) sel[r] = 0ull;
    __syncthreads();
    bitonic_desc_u64(sel, 1024);
    __syncthreads();
    for (int r = tid; r < K2; r += 512){
        unsigned long long cc = sel[r];
        float* o = out + ((size_t)b*1000 + r)*5;
        if ((unsigned)(cc >> 32) & 0x80000000u){
            int pos = (int)(0xFFFFFFFFu - (unsigned)(cc & 0xFFFFFFFFull));
            float4 bx = g_boxes[b*KTOT + pos];
            o[0] = bx.x; o[1] = bx.y; o[2] = bx.z; o[3] = bx.w;
            o[4] = g_scores[b*KTOT + pos];
        } else {
            o[0] = 0.f; o[1] = 0.f; o[2] = 0.f; o[3] = 0.f; o[4] = 0.f;
        }
    }
}

extern "C" void kernel_launch(void* const* d_in, const int* in_sizes, int n_in,
                              void* d_out, int out_size){
    const float* obj     = (const float*)d_in[0];
    const float* deltas  = (const float*)d_in[1];
    const float* anchors = (const float*)d_in[2];
    float* out = (float*)d_out;

    const int DSM_SEL = SCAP*8 + 1024*8 + 2048*4 + 1024*4;  /* 86016  */
    const int DSM_B   = 1024*ROWW*8;                         /* 131072 */
    cudaFuncSetAttribute(select_kernel, cudaFuncAttributeMaxDynamicSharedMemorySize, DSM_SEL);
    cudaFuncSetAttribute(nmsB_kernel,   cudaFuncAttributeMaxDynamicSharedMemorySize, DSM_B);

    cand_kernel  <<<dim3(5, BB, CH1), 256>>>(obj);
    select_kernel<<<dim3(5, BB), 512, DSM_SEL>>>(obj, deltas, anchors);
    nmsA_kernel  <<<dim3(5, BB, 16), 128>>>();
    nmsB_kernel  <<<dim3(5, BB), 512, DSM_B>>>();
    final_kernel <<<BB, 512>>>(out);
}